// round 14
// baseline (speedup 1.0000x reference)
#include <cuda_runtime.h>
#include <cuda_bf16.h>
#include <cuda_fp16.h>
#include <cstdint>
#include <cstring>

// Problem constants
constexpr int kB = 2;
constexpr int kS = 2048;
constexpr int kE = 1024;
constexpr int kH = 16;
constexpr int kD = 64;
constexpr int kM = kB * kS;  // 4096

// Scratch (static device globals)
__device__ __nv_bfloat16 g_encb[(size_t)kM * kE];
__device__ __nv_bfloat16 g_decb[(size_t)kM * kE];
__device__ __nv_bfloat16 g_wq[(size_t)kE * kE];  // [E][HD] n-major, pre-scaled
__device__ __nv_bfloat16 g_wk[(size_t)kE * kE];
__device__ __nv_bfloat16 g_wv[(size_t)kE * kE];
__device__ __nv_bfloat16 g_wo[(size_t)kE * kE];  // [HD][E] native
__device__ __nv_bfloat16 g_qb[(size_t)kB * kH * kS * kD];  // bf16 (scale in Wq)
__device__ __nv_bfloat16 g_kb[(size_t)kB * kH * kS * kD];  // bf16
__device__ __nv_bfloat16 g_vb[(size_t)kB * kH * kS * kD];  // fp16 bits
__device__ __nv_bfloat16 g_ctxb[(size_t)kM * kE];          // bf16 [b,s,h*D]
__device__ __half g_x[(size_t)kM * kE];                    // pre-LN, fp16

// ---------------------------------------------------------------------------
// PTX helpers
// ---------------------------------------------------------------------------
__device__ __forceinline__ unsigned smem_u32(const void* p) {
  return (unsigned)__cvta_generic_to_shared(p);
}
__device__ __forceinline__ void ldsm4(unsigned* r, unsigned a) {
  asm volatile(
      "ldmatrix.sync.aligned.m8n8.x4.shared.b16 {%0,%1,%2,%3},[%4];\n"
      : "=r"(r[0]), "=r"(r[1]), "=r"(r[2]), "=r"(r[3])
      : "r"(a));
}
__device__ __forceinline__ void ldsm4t(unsigned* r, unsigned a) {
  asm volatile(
      "ldmatrix.sync.aligned.m8n8.x4.trans.shared.b16 {%0,%1,%2,%3},[%4];\n"
      : "=r"(r[0]), "=r"(r[1]), "=r"(r[2]), "=r"(r[3])
      : "r"(a));
}
__device__ __forceinline__ void mma16816(float* d, const unsigned* a, unsigned b0,
                                         unsigned b1) {
  asm volatile(
      "mma.sync.aligned.m16n8k16.row.col.f32.bf16.bf16.f32 "
      "{%0,%1,%2,%3},{%4,%5,%6,%7},{%8,%9},{%0,%1,%2,%3};\n"
      : "+f"(d[0]), "+f"(d[1]), "+f"(d[2]), "+f"(d[3])
      : "r"(a[0]), "r"(a[1]), "r"(a[2]), "r"(a[3]), "r"(b0), "r"(b1));
}
__device__ __forceinline__ void mma16816h(float* d, const unsigned* a, unsigned b0,
                                          unsigned b1) {
  asm volatile(
      "mma.sync.aligned.m16n8k16.row.col.f32.f16.f16.f32 "
      "{%0,%1,%2,%3},{%4,%5,%6,%7},{%8,%9},{%0,%1,%2,%3};\n"
      : "+f"(d[0]), "+f"(d[1]), "+f"(d[2]), "+f"(d[3])
      : "r"(a[0]), "r"(a[1]), "r"(a[2]), "r"(a[3]), "r"(b0), "r"(b1));
}
__device__ __forceinline__ void cpasync16(unsigned s, const void* g) {
  asm volatile("cp.async.cg.shared.global [%0],[%1],16;\n" ::"r"(s), "l"(g)
               : "memory");
}
__device__ __forceinline__ void cp_commit() {
  asm volatile("cp.async.commit_group;\n" ::: "memory");
}
__device__ __forceinline__ void cp_wait2() {
  asm volatile("cp.async.wait_group 2;\n" ::: "memory");
}
__device__ __forceinline__ unsigned pack_bf16x2(float lo, float hi) {
  __nv_bfloat162 t = __floats2bfloat162_rn(lo, hi);
  unsigned u;
  memcpy(&u, &t, 4);
  return u;
}
__device__ __forceinline__ unsigned pack_f16x2(float lo, float hi) {
  unsigned u;
  asm("cvt.rn.f16x2.f32 %0, %1, %2;" : "=r"(u) : "f"(hi), "f"(lo));
  return u;
}
__device__ __forceinline__ unsigned ex2h2(unsigned x) {
  unsigned r;
  asm("ex2.approx.f16x2 %0, %1;" : "=r"(r) : "r"(x));
  return r;
}
__device__ __forceinline__ unsigned hadd2u(unsigned a, unsigned b) {
  unsigned r;
  asm("add.f16x2 %0, %1, %2;" : "=r"(r) : "r"(a), "r"(b));
  return r;
}
__device__ __forceinline__ float2 h2_to_f2(unsigned u) {
  __half2 h;
  memcpy(&h, &u, 4);
  return __half22float2(h);
}

// ---------------------------------------------------------------------------
// Unified converter: ONE launch for all 6 conversion tasks.
// z=0: enc->g_encb, z=1: dec->g_decb (plain, 4M elems each)
// z=2..4: Wq/Wk/Wv [H][E][D] -> [E][H*D] scatter (Wq scaled by log2e/8)
// z=5: Wo plain copy
// ---------------------------------------------------------------------------
__global__ __launch_bounds__(256) void cvt_all(
    const float* __restrict__ enc, const float* __restrict__ dec,
    const float* __restrict__ wq, const float* __restrict__ wk,
    const float* __restrict__ wv, const float* __restrict__ wo) {
  const int z = blockIdx.z;
  const int nblk = (z < 2) ? (kM * kE / 4096) : (kE * kE / 4096);
  if (blockIdx.x >= nblk) return;
  size_t i = ((size_t)blockIdx.x * 256 + threadIdx.x) * 16;

  const float* src;
  switch (z) {
    case 0: src = enc; break;
    case 1: src = dec; break;
    case 2: src = wq; break;
    case 3: src = wk; break;
    case 4: src = wv; break;
    default: src = wo; break;
  }
  const float scl = (z == 2) ? 0.125f * 1.4426950408889634f : 1.0f;
  float4 v0 = *(const float4*)(src + i);
  float4 v1 = *(const float4*)(src + i + 4);
  float4 v2 = *(const float4*)(src + i + 8);
  float4 v3 = *(const float4*)(src + i + 12);
  unsigned p[8];
  p[0] = pack_bf16x2(v0.x * scl, v0.y * scl);
  p[1] = pack_bf16x2(v0.z * scl, v0.w * scl);
  p[2] = pack_bf16x2(v1.x * scl, v1.y * scl);
  p[3] = pack_bf16x2(v1.z * scl, v1.w * scl);
  p[4] = pack_bf16x2(v2.x * scl, v2.y * scl);
  p[5] = pack_bf16x2(v2.z * scl, v2.w * scl);
  p[6] = pack_bf16x2(v3.x * scl, v3.y * scl);
  p[7] = pack_bf16x2(v3.z * scl, v3.w * scl);

  __nv_bfloat16* o;
  if (z == 0) {
    o = g_encb + i;
  } else if (z == 1) {
    o = g_decb + i;
  } else if (z == 5) {
    o = g_wo + i;
  } else {
    __nv_bfloat16* dst = (z == 2) ? g_wq : (z == 3) ? g_wk : g_wv;
    int h = (int)(i >> 16);
    int rem = (int)(i & 65535);
    int e = rem >> 6;
    int d = rem & 63;
    o = dst + (size_t)e * kE + h * kD + d;
  }
  *(uint4*)o = *(uint4*)&p[0];
  *(uint4*)(o + 8) = *(uint4*)&p[4];
}

// ---------------------------------------------------------------------------
// bf16 HMMA GEMM (R11-proven): CTA 64x128x32, 128 threads / 4 warps (2m x 2n),
// warp tile 32x64. B [K][N] n-major, ldsm4t. 4-stage ring, 3 CTAs/SM.
// MODE 0: merged QKV via blockIdx.z (z==2 packs fp16 for V).
// MODE 1: out-proj + fp32 residual -> g_x (fp16).
// ---------------------------------------------------------------------------
constexpr int APAD = 40;
constexpr int BPAD = 136;
constexpr int A_STG = 64 * APAD;   // 2560
constexpr int B_STG = 32 * BPAD;   // 4352
constexpr int GEMM_SMEM = 4 * (A_STG + B_STG) * 2;  // 55296 B

template <int MODE>
__global__ __launch_bounds__(128, 3) void gemm_tc(const float* __restrict__ resid) {
  extern __shared__ __nv_bfloat16 gsm[];
  __nv_bfloat16* AsB = gsm;              // [4][64][APAD]
  __nv_bfloat16* BsB = gsm + 4 * A_STG;  // [4][32][BPAD]

  const int tid = threadIdx.x;
  const int lane = tid & 31;
  const int w = tid >> 5;  // 0..3
  const int m0 = blockIdx.y * 64;
  const int n0 = blockIdx.x * 128;
  const int wm = (w >> 1) * 32;
  const int wn = (w & 1) * 64;

  const __nv_bfloat16* A;
  const __nv_bfloat16* Bw;
  __nv_bfloat16* out = nullptr;
  int z = 0;
  if (MODE == 0) {
    z = blockIdx.z;
    A = (z == 0) ? g_decb : g_encb;
    Bw = (z == 0) ? g_wq : (z == 1) ? g_wk : g_wv;
    out = (z == 0) ? g_qb : (z == 1) ? g_kb : g_vb;
  } else {
    A = g_ctxb;
    Bw = g_wo;
  }

  auto load_stage = [&](int j) {
    const int stg = j & 3;
    __nv_bfloat16* as = AsB + stg * A_STG;
    __nv_bfloat16* bs = BsB + stg * B_STG;
    const int k0 = j * 32;
#pragma unroll
    for (int it = 0; it < 2; it++) {
      int ch = tid + it * 128;
      int rowA = ch >> 2, cA = (ch & 3) * 8;
      cpasync16(smem_u32(as + rowA * APAD + cA),
                A + (size_t)(m0 + rowA) * kE + k0 + cA);
    }
#pragma unroll
    for (int it = 0; it < 4; it++) {
      int ch = tid + it * 128;
      int rowB = ch >> 4, cB = (ch & 15) * 8;
      cpasync16(smem_u32(bs + rowB * BPAD + cB),
                Bw + (size_t)(k0 + rowB) * kE + n0 + cB);
    }
  };

#pragma unroll
  for (int s = 0; s < 3; s++) {
    load_stage(s);
    cp_commit();
  }

  float acc[2][8][4];
#pragma unroll
  for (int mi = 0; mi < 2; mi++)
#pragma unroll
    for (int nf = 0; nf < 8; nf++)
#pragma unroll
      for (int c = 0; c < 4; c++) acc[mi][nf][c] = 0.f;

  const int lr = lane & 15;
  const int lc = lane >> 4;

  const int nK = kE / 32;  // 32
  for (int kt = 0; kt < nK; kt++) {
    cp_wait2();
    __syncthreads();
    if (kt + 3 < nK) load_stage(kt + 3);
    cp_commit();

    const __nv_bfloat16* as = AsB + (kt & 3) * A_STG;
    const __nv_bfloat16* bs = BsB + (kt & 3) * B_STG;
#pragma unroll
    for (int ks = 0; ks < 2; ks++) {
      const int kk = ks * 16;
      unsigned af[2][4];
#pragma unroll
      for (int mi = 0; mi < 2; mi++)
        ldsm4(af[mi], smem_u32(as + (wm + mi * 16 + lr) * APAD + kk + lc * 8));
#pragma unroll
      for (int nj = 0; nj < 4; nj++) {
        unsigned bfr[4];
        ldsm4t(bfr, smem_u32(bs + (kk + lr) * BPAD + wn + nj * 16 + lc * 8));
#pragma unroll
        for (int mi = 0; mi < 2; mi++) {
          mma16816(acc[mi][2 * nj + 0], af[mi], bfr[0], bfr[1]);
          mma16816(acc[mi][2 * nj + 1], af[mi], bfr[2], bfr[3]);
        }
      }
    }
  }

  // epilogue
  const int g = lane >> 2;
  const int t4 = lane & 3;
  if (MODE == 0) {
    const bool f16out = (z == 2);
#pragma unroll
    for (int mi = 0; mi < 2; mi++) {
      int mrow = m0 + wm + mi * 16 + g;
      int b = mrow >> 11;
      int s = mrow & (kS - 1);
#pragma unroll
      for (int nf = 0; nf < 8; nf++) {
        int n = n0 + wn + nf * 8 + 2 * t4;
        int h = n >> 6;
        int d = n & 63;
        __nv_bfloat16* base = out + (((size_t)b * kH + h) * kS) * kD + d;
        unsigned p0, p1;
        if (f16out) {
          p0 = pack_f16x2(acc[mi][nf][0], acc[mi][nf][1]);
          p1 = pack_f16x2(acc[mi][nf][2], acc[mi][nf][3]);
        } else {
          p0 = pack_bf16x2(acc[mi][nf][0], acc[mi][nf][1]);
          p1 = pack_bf16x2(acc[mi][nf][2], acc[mi][nf][3]);
        }
        *(unsigned*)(base + (size_t)s * kD) = p0;
        *(unsigned*)(base + (size_t)(s + 8) * kD) = p1;
      }
    }
  } else {
#pragma unroll
    for (int mi = 0; mi < 2; mi++) {
      size_t m1 = (size_t)(m0 + wm + mi * 16 + g);
      size_t m2 = m1 + 8;
#pragma unroll
      for (int nf = 0; nf < 8; nf++) {
        int n = n0 + wn + nf * 8 + 2 * t4;
        float2 r0 = *(const float2*)(resid + m1 * kE + n);
        float2 r1 = *(const float2*)(resid + m2 * kE + n);
        *(unsigned*)(g_x + m1 * kE + n) =
            pack_f16x2(acc[mi][nf][0] + r0.x, acc[mi][nf][1] + r0.y);
        *(unsigned*)(g_x + m2 * kE + n) =
            pack_f16x2(acc[mi][nf][2] + r1.x, acc[mi][nf][3] + r1.y);
      }
    }
  }
}

// ---------------------------------------------------------------------------
// Flash attention (R10 exact config): TQ=128, 4 warps x 32 q-rows, Tk=64,
// 4-stage cp.async ring, occ 2. QK bf16 MMA (log2 scores, scale in Wq),
// exp via ex2.approx.f16x2 (result IS the fp16 P fragment), PV fp16 MMA.
// ---------------------------------------------------------------------------
constexpr int TQ = 128;
constexpr int TK = 64;
constexpr int PAD = 72;
constexpr int KV_STG = TK * PAD;
constexpr int ATTN_SMEM = (TQ * PAD + 2 * 4 * KV_STG) * 2;  // 92160 B

__global__ __launch_bounds__(128, 2) void attn_kernel() {
  extern __shared__ __nv_bfloat16 sm[];
  __nv_bfloat16* Qs = sm;               // [128][72]
  __nv_bfloat16* Ks = sm + TQ * PAD;    // [4][64][72]
  __nv_bfloat16* Vs = Ks + 4 * KV_STG;  // [4][64][72] (fp16 bits)

  const int tid = threadIdx.x;
  const int lane = tid & 31;
  const int w = tid >> 5;  // 0..3
  const int bh = blockIdx.y;
  const int q0 = blockIdx.x * TQ;

  const __nv_bfloat16* gq = g_qb + (size_t)bh * kS * kD + (size_t)q0 * kD;
  const __nv_bfloat16* gk = g_kb + (size_t)bh * kS * kD;
  const __nv_bfloat16* gv = g_vb + (size_t)bh * kS * kD;

  auto load_kv = [&](int stg, int tile) {
    const __nv_bfloat16* k2 = gk + (size_t)tile * TK * kD;
    const __nv_bfloat16* v2 = gv + (size_t)tile * TK * kD;
#pragma unroll
    for (int it = 0; it < 4; it++) {
      int ch = tid + it * 128;
      int row = ch >> 3, c = (ch & 7) * 8;
      cpasync16(smem_u32(Ks + stg * KV_STG + row * PAD + c),
                k2 + (size_t)row * kD + c);
      cpasync16(smem_u32(Vs + stg * KV_STG + row * PAD + c),
                v2 + (size_t)row * kD + c);
    }
  };

#pragma unroll
  for (int s = 0; s < 3; s++) {
    load_kv(s, s);
    cp_commit();
  }

  for (int idx = tid; idx < TQ * 8; idx += 128) {
    int row = idx >> 3, c = (idx & 7) * 8;
    *(uint4*)(Qs + row * PAD + c) = *(const uint4*)(gq + (size_t)row * kD + c);
  }
  __syncthreads();

  const int lr = lane & 15;
  const int lc = lane >> 4;
  unsigned qa[2][4][4];
#pragma unroll
  for (int mi = 0; mi < 2; mi++) {
    const __nv_bfloat16* qp = Qs + (w * 32 + mi * 16 + lr) * PAD + lc * 8;
#pragma unroll
    for (int kt = 0; kt < 4; kt++) ldsm4(qa[mi][kt], smem_u32(qp + kt * 16));
  }

  float oa[2][8][4];
#pragma unroll
  for (int mi = 0; mi < 2; mi++)
#pragma unroll
    for (int j = 0; j < 8; j++)
#pragma unroll
      for (int c = 0; c < 4; c++) oa[mi][j][c] = 0.f;
  float lsum[2][2] = {{0.f, 0.f}, {0.f, 0.f}};

  const int nT = kS / TK;  // 32
  for (int ti = 0; ti < nT; ti++) {
    const int stg = ti & 3;
    cp_wait2();
    __syncthreads();
    if (ti + 3 < nT) load_kv((ti + 3) & 3, ti + 3);
    cp_commit();

    const __nv_bfloat16* kbp = Ks + stg * KV_STG;
    const __nv_bfloat16* vbp = Vs + stg * KV_STG;

    float sc[2][8][4];
#pragma unroll
    for (int mi = 0; mi < 2; mi++)
#pragma unroll
      for (int j = 0; j < 8; j++)
#pragma unroll
        for (int c = 0; c < 4; c++) sc[mi][j][c] = 0.f;
#pragma unroll
    for (int kt = 0; kt < 4; kt++) {
#pragma unroll
      for (int ng = 0; ng < 4; ng++) {
        unsigned kr[4];
        ldsm4(kr, smem_u32(kbp + (ng * 16 + lr) * PAD + kt * 16 + lc * 8));
#pragma unroll
        for (int mi = 0; mi < 2; mi++) {
          mma16816(sc[mi][2 * ng + 0], qa[mi][kt], kr[0], kr[2]);
          mma16816(sc[mi][2 * ng + 1], qa[mi][kt], kr[1], kr[3]);
        }
      }
    }

    unsigned pa[2][4][4];
#pragma unroll
    for (int mi = 0; mi < 2; mi++) {
      unsigned a0 = 0, a1 = 0;
#pragma unroll
      for (int j = 0; j < 8; j++) {
        unsigned s01 = pack_f16x2(sc[mi][j][0], sc[mi][j][1]);
        unsigned s23 = pack_f16x2(sc[mi][j][2], sc[mi][j][3]);
        unsigned w01 = ex2h2(s01);
        unsigned w23 = ex2h2(s23);
        a0 = hadd2u(a0, w01);
        a1 = hadd2u(a1, w23);
        int q = j >> 1;
        if (j & 1) {
          pa[mi][q][2] = w01;
          pa[mi][q][3] = w23;
        } else {
          pa[mi][q][0] = w01;
          pa[mi][q][1] = w23;
        }
      }
      float2 f0 = h2_to_f2(a0);
      float2 f1 = h2_to_f2(a1);
      lsum[mi][0] += f0.x + f0.y;
      lsum[mi][1] += f1.x + f1.y;
    }

#pragma unroll
    for (int kt = 0; kt < 4; kt++) {
#pragma unroll
      for (int dg = 0; dg < 4; dg++) {
        unsigned vr[4];
        ldsm4t(vr, smem_u32(vbp + (kt * 16 + lr) * PAD + dg * 16 + lc * 8));
#pragma unroll
        for (int mi = 0; mi < 2; mi++) {
          mma16816h(oa[mi][2 * dg + 0], pa[mi][kt], vr[0], vr[1]);
          mma16816h(oa[mi][2 * dg + 1], pa[mi][kt], vr[2], vr[3]);
        }
      }
    }
  }

  const int g = lane >> 2, t = lane & 3;
  const int b = bh >> 4, h = bh & 15;
#pragma unroll
  for (int mi = 0; mi < 2; mi++) {
    float l0 = lsum[mi][0], l1 = lsum[mi][1];
    l0 += __shfl_xor_sync(0xffffffffu, l0, 1);
    l0 += __shfl_xor_sync(0xffffffffu, l0, 2);
    l1 += __shfl_xor_sync(0xffffffffu, l1, 1);
    l1 += __shfl_xor_sync(0xffffffffu, l1, 2);
    const float il0 = 1.f / l0;
    const float il1 = 1.f / l1;
    const size_t row0 = (size_t)b * kS + q0 + w * 32 + mi * 16 + g;
    __nv_bfloat16* base0 = g_ctxb + row0 * kE + h * 64 + 2 * t;
    __nv_bfloat16* base1 = base0 + (size_t)8 * kE;
#pragma unroll
    for (int j = 0; j < 8; j++) {
      *(unsigned*)(base0 + 8 * j) =
          pack_bf16x2(oa[mi][j][0] * il0, oa[mi][j][1] * il0);
      *(unsigned*)(base1 + 8 * j) =
          pack_bf16x2(oa[mi][j][2] * il1, oa[mi][j][3] * il1);
    }
  }
}

// ---------------------------------------------------------------------------
// LayerNorm over last dim (1024): reads fp16 g_x, writes fp32 out.
// ---------------------------------------------------------------------------
__global__ __launch_bounds__(256) void ln_kernel(
    const float* __restrict__ gamma, const float* __restrict__ beta,
    float* __restrict__ out) {
  __shared__ float red[8];
  __shared__ float red2[8];
  const int m = blockIdx.x;
  const int tid = threadIdx.x;
  uint2 raw = *(const uint2*)(g_x + (size_t)m * kE + tid * 4);
  float2 a = h2_to_f2(raw.x);
  float2 bb = h2_to_f2(raw.y);
  float vx = a.x, vy = a.y, vz = bb.x, vw = bb.y;
  float s = vx + vy + vz + vw;
#pragma unroll
  for (int off = 16; off > 0; off >>= 1) s += __shfl_xor_sync(0xffffffffu, s, off);
  if ((tid & 31) == 0) red[tid >> 5] = s;
  __syncthreads();
  float tot = red[0] + red[1] + red[2] + red[3] + red[4] + red[5] + red[6] + red[7];
  float mu = tot * (1.f / kE);
  float dx = vx - mu, dy = vy - mu, dz = vz - mu, dw = vw - mu;
  float sq = dx * dx + dy * dy + dz * dz + dw * dw;
#pragma unroll
  for (int off = 16; off > 0; off >>= 1) sq += __shfl_xor_sync(0xffffffffu, sq, off);
  if ((tid & 31) == 0) red2[tid >> 5] = sq;
  __syncthreads();
  float var =
      (red2[0] + red2[1] + red2[2] + red2[3] + red2[4] + red2[5] + red2[6] + red2[7]) *
      (1.f / kE);
  float rstd = rsqrtf(var + 1e-5f);
  float4 g = *(const float4*)(gamma + tid * 4);
  float4 be = *(const float4*)(beta + tid * 4);
  float4 o = make_float4(dx * rstd * g.x + be.x, dy * rstd * g.y + be.y,
                         dz * rstd * g.z + be.z, dw * rstd * g.w + be.w);
  *(float4*)(out + (size_t)m * kE + tid * 4) = o;
}

// ---------------------------------------------------------------------------
extern "C" void kernel_launch(void* const* d_in, const int* in_sizes, int n_in,
                              void* d_out, int out_size) {
  const float* enc = (const float*)d_in[0];
  const float* dec = (const float*)d_in[1];
  const float* Wq = (const float*)d_in[2];
  const float* Wk = (const float*)d_in[3];
  const float* Wv = (const float*)d_in[4];
  const float* Wo = (const float*)d_in[5];
  const float* gamma = (const float*)d_in[6];
  const float* beta = (const float*)d_in[7];
  float* out = (float*)d_out;

  cudaFuncSetAttribute(attn_kernel, cudaFuncAttributeMaxDynamicSharedMemorySize,
                       ATTN_SMEM);
  cudaFuncSetAttribute(gemm_tc<0>, cudaFuncAttributeMaxDynamicSharedMemorySize,
                       GEMM_SMEM);
  cudaFuncSetAttribute(gemm_tc<1>, cudaFuncAttributeMaxDynamicSharedMemorySize,
                       GEMM_SMEM);

  // all converts in ONE launch (z = 0..5)
  cvt_all<<<dim3(kM * kE / 4096, 1, 6), 256>>>(enc, dec, Wq, Wk, Wv, Wo);

  // merged QKV GEMM: grid (N/128, M/64, 3) = 1536 CTAs
  gemm_tc<0><<<dim3(kE / 128, kM / 64, 3), 128, GEMM_SMEM>>>(nullptr);
  attn_kernel<<<dim3(kS / TQ, kB * kH), 128, ATTN_SMEM>>>();
  gemm_tc<1><<<dim3(kE / 128, kM / 64), 128, GEMM_SMEM>>>(dec);
  ln_kernel<<<kM, 256>>>(gamma, beta, out);
}

// round 15
// speedup vs baseline: 1.0001x; 1.0001x over previous
#include <cuda_runtime.h>
#include <cuda_bf16.h>
#include <cuda_fp16.h>
#include <cstdint>
#include <cstring>

// Problem constants
constexpr int kB = 2;
constexpr int kS = 2048;
constexpr int kE = 1024;
constexpr int kH = 16;
constexpr int kD = 64;
constexpr int kM = kB * kS;  // 4096

// Scratch (static device globals)
__device__ __nv_bfloat16 g_encb[(size_t)kM * kE];
__device__ __nv_bfloat16 g_decb[(size_t)kM * kE];
__device__ __nv_bfloat16 g_wq[(size_t)kE * kE];  // [E][HD] n-major, pre-scaled
__device__ __nv_bfloat16 g_wk[(size_t)kE * kE];
__device__ __nv_bfloat16 g_wv[(size_t)kE * kE];
__device__ __nv_bfloat16 g_wo[(size_t)kE * kE];  // [HD][E] native
__device__ __nv_bfloat16 g_qb[(size_t)kB * kH * kS * kD];  // bf16 (scale in Wq)
__device__ __nv_bfloat16 g_kb[(size_t)kB * kH * kS * kD];  // bf16
__device__ __nv_bfloat16 g_vb[(size_t)kB * kH * kS * kD];  // fp16 bits
__device__ __nv_bfloat16 g_ctxb[(size_t)kM * kE];          // bf16 [b,s,h*D]
__device__ float g_x[(size_t)kM * kE];                     // pre-LN, fp32

// ---------------------------------------------------------------------------
// PTX helpers
// ---------------------------------------------------------------------------
__device__ __forceinline__ unsigned smem_u32(const void* p) {
  return (unsigned)__cvta_generic_to_shared(p);
}
__device__ __forceinline__ void ldsm4(unsigned* r, unsigned a) {
  asm volatile(
      "ldmatrix.sync.aligned.m8n8.x4.shared.b16 {%0,%1,%2,%3},[%4];\n"
      : "=r"(r[0]), "=r"(r[1]), "=r"(r[2]), "=r"(r[3])
      : "r"(a));
}
__device__ __forceinline__ void ldsm4t(unsigned* r, unsigned a) {
  asm volatile(
      "ldmatrix.sync.aligned.m8n8.x4.trans.shared.b16 {%0,%1,%2,%3},[%4];\n"
      : "=r"(r[0]), "=r"(r[1]), "=r"(r[2]), "=r"(r[3])
      : "r"(a));
}
__device__ __forceinline__ void mma16816(float* d, const unsigned* a, unsigned b0,
                                         unsigned b1) {
  asm volatile(
      "mma.sync.aligned.m16n8k16.row.col.f32.bf16.bf16.f32 "
      "{%0,%1,%2,%3},{%4,%5,%6,%7},{%8,%9},{%0,%1,%2,%3};\n"
      : "+f"(d[0]), "+f"(d[1]), "+f"(d[2]), "+f"(d[3])
      : "r"(a[0]), "r"(a[1]), "r"(a[2]), "r"(a[3]), "r"(b0), "r"(b1));
}
__device__ __forceinline__ void mma16816h(float* d, const unsigned* a, unsigned b0,
                                          unsigned b1) {
  asm volatile(
      "mma.sync.aligned.m16n8k16.row.col.f32.f16.f16.f32 "
      "{%0,%1,%2,%3},{%4,%5,%6,%7},{%8,%9},{%0,%1,%2,%3};\n"
      : "+f"(d[0]), "+f"(d[1]), "+f"(d[2]), "+f"(d[3])
      : "r"(a[0]), "r"(a[1]), "r"(a[2]), "r"(a[3]), "r"(b0), "r"(b1));
}
__device__ __forceinline__ void cpasync16(unsigned s, const void* g) {
  asm volatile("cp.async.cg.shared.global [%0],[%1],16;\n" ::"r"(s), "l"(g)
               : "memory");
}
__device__ __forceinline__ void cp_commit() {
  asm volatile("cp.async.commit_group;\n" ::: "memory");
}
__device__ __forceinline__ void cp_wait2() {
  asm volatile("cp.async.wait_group 2;\n" ::: "memory");
}
__device__ __forceinline__ unsigned pack_bf16x2(float lo, float hi) {
  __nv_bfloat162 t = __floats2bfloat162_rn(lo, hi);
  unsigned u;
  memcpy(&u, &t, 4);
  return u;
}
__device__ __forceinline__ unsigned pack_f16x2(float lo, float hi) {
  unsigned u;
  asm("cvt.rn.f16x2.f32 %0, %1, %2;" : "=r"(u) : "f"(hi), "f"(lo));
  return u;
}
__device__ __forceinline__ unsigned ex2h2(unsigned x) {
  unsigned r;
  asm("ex2.approx.f16x2 %0, %1;" : "=r"(r) : "r"(x));
  return r;
}
__device__ __forceinline__ unsigned hadd2u(unsigned a, unsigned b) {
  unsigned r;
  asm("add.f16x2 %0, %1, %2;" : "=r"(r) : "r"(a), "r"(b));
  return r;
}
__device__ __forceinline__ float2 h2_to_f2(unsigned u) {
  __half2 h;
  memcpy(&h, &u, 4);
  return __half22float2(h);
}

// ---------------------------------------------------------------------------
// Unified converter: ONE launch for all 6 conversion tasks.
// z=0: enc->g_encb, z=1: dec->g_decb; z=2..4: Wq/Wk/Wv scatter (Wq scaled);
// z=5: Wo plain copy.
// ---------------------------------------------------------------------------
__global__ __launch_bounds__(256) void cvt_all(
    const float* __restrict__ enc, const float* __restrict__ dec,
    const float* __restrict__ wq, const float* __restrict__ wk,
    const float* __restrict__ wv, const float* __restrict__ wo) {
  const int z = blockIdx.z;
  const int nblk = (z < 2) ? (kM * kE / 4096) : (kE * kE / 4096);
  if (blockIdx.x >= nblk) return;
  size_t i = ((size_t)blockIdx.x * 256 + threadIdx.x) * 16;

  const float* src;
  switch (z) {
    case 0: src = enc; break;
    case 1: src = dec; break;
    case 2: src = wq; break;
    case 3: src = wk; break;
    case 4: src = wv; break;
    default: src = wo; break;
  }
  const float scl = (z == 2) ? 0.125f * 1.4426950408889634f : 1.0f;
  float4 v0 = *(const float4*)(src + i);
  float4 v1 = *(const float4*)(src + i + 4);
  float4 v2 = *(const float4*)(src + i + 8);
  float4 v3 = *(const float4*)(src + i + 12);
  unsigned p[8];
  p[0] = pack_bf16x2(v0.x * scl, v0.y * scl);
  p[1] = pack_bf16x2(v0.z * scl, v0.w * scl);
  p[2] = pack_bf16x2(v1.x * scl, v1.y * scl);
  p[3] = pack_bf16x2(v1.z * scl, v1.w * scl);
  p[4] = pack_bf16x2(v2.x * scl, v2.y * scl);
  p[5] = pack_bf16x2(v2.z * scl, v2.w * scl);
  p[6] = pack_bf16x2(v3.x * scl, v3.y * scl);
  p[7] = pack_bf16x2(v3.z * scl, v3.w * scl);

  __nv_bfloat16* o;
  if (z == 0) {
    o = g_encb + i;
  } else if (z == 1) {
    o = g_decb + i;
  } else if (z == 5) {
    o = g_wo + i;
  } else {
    __nv_bfloat16* dst = (z == 2) ? g_wq : (z == 3) ? g_wk : g_wv;
    int h = (int)(i >> 16);
    int rem = (int)(i & 65535);
    int e = rem >> 6;
    int d = rem & 63;
    o = dst + (size_t)e * kE + h * kD + d;
  }
  *(uint4*)o = *(uint4*)&p[0];
  *(uint4*)(o + 8) = *(uint4*)&p[4];
}

// ---------------------------------------------------------------------------
// QKV GEMM (R11-proven): CTA 64x128x32, 128 threads / 4 warps (2m x 2n),
// warp tile 32x64. B [K][N] n-major, ldsm4t. 4-stage ring, 3 CTAs/SM.
// blockIdx.z selects Q/K/V (z==2 packs fp16 for V; Q scale folded into Wq).
// ---------------------------------------------------------------------------
constexpr int APAD = 40;
constexpr int BPAD = 136;
constexpr int A_STG = 64 * APAD;   // 2560
constexpr int B_STG = 32 * BPAD;   // 4352
constexpr int GEMM_SMEM = 4 * (A_STG + B_STG) * 2;  // 55296 B

__global__ __launch_bounds__(128, 3) void gemm_qkv() {
  extern __shared__ __nv_bfloat16 gsm[];
  __nv_bfloat16* AsB = gsm;              // [4][64][APAD]
  __nv_bfloat16* BsB = gsm + 4 * A_STG;  // [4][32][BPAD]

  const int tid = threadIdx.x;
  const int lane = tid & 31;
  const int w = tid >> 5;  // 0..3
  const int m0 = blockIdx.y * 64;
  const int n0 = blockIdx.x * 128;
  const int wm = (w >> 1) * 32;
  const int wn = (w & 1) * 64;

  const int z = blockIdx.z;
  const __nv_bfloat16* A = (z == 0) ? g_decb : g_encb;
  const __nv_bfloat16* Bw = (z == 0) ? g_wq : (z == 1) ? g_wk : g_wv;
  __nv_bfloat16* out = (z == 0) ? g_qb : (z == 1) ? g_kb : g_vb;

  auto load_stage = [&](int j) {
    const int stg = j & 3;
    __nv_bfloat16* as = AsB + stg * A_STG;
    __nv_bfloat16* bs = BsB + stg * B_STG;
    const int k0 = j * 32;
#pragma unroll
    for (int it = 0; it < 2; it++) {
      int ch = tid + it * 128;
      int rowA = ch >> 2, cA = (ch & 3) * 8;
      cpasync16(smem_u32(as + rowA * APAD + cA),
                A + (size_t)(m0 + rowA) * kE + k0 + cA);
    }
#pragma unroll
    for (int it = 0; it < 4; it++) {
      int ch = tid + it * 128;
      int rowB = ch >> 4, cB = (ch & 15) * 8;
      cpasync16(smem_u32(bs + rowB * BPAD + cB),
                Bw + (size_t)(k0 + rowB) * kE + n0 + cB);
    }
  };

#pragma unroll
  for (int s = 0; s < 3; s++) {
    load_stage(s);
    cp_commit();
  }

  float acc[2][8][4];
#pragma unroll
  for (int mi = 0; mi < 2; mi++)
#pragma unroll
    for (int nf = 0; nf < 8; nf++)
#pragma unroll
      for (int c = 0; c < 4; c++) acc[mi][nf][c] = 0.f;

  const int lr = lane & 15;
  const int lc = lane >> 4;

  const int nK = kE / 32;  // 32
  for (int kt = 0; kt < nK; kt++) {
    cp_wait2();
    __syncthreads();
    if (kt + 3 < nK) load_stage(kt + 3);
    cp_commit();

    const __nv_bfloat16* as = AsB + (kt & 3) * A_STG;
    const __nv_bfloat16* bs = BsB + (kt & 3) * B_STG;
#pragma unroll
    for (int ks = 0; ks < 2; ks++) {
      const int kk = ks * 16;
      unsigned af[2][4];
#pragma unroll
      for (int mi = 0; mi < 2; mi++)
        ldsm4(af[mi], smem_u32(as + (wm + mi * 16 + lr) * APAD + kk + lc * 8));
#pragma unroll
      for (int nj = 0; nj < 4; nj++) {
        unsigned bfr[4];
        ldsm4t(bfr, smem_u32(bs + (kk + lr) * BPAD + wn + nj * 16 + lc * 8));
#pragma unroll
        for (int mi = 0; mi < 2; mi++) {
          mma16816(acc[mi][2 * nj + 0], af[mi], bfr[0], bfr[1]);
          mma16816(acc[mi][2 * nj + 1], af[mi], bfr[2], bfr[3]);
        }
      }
    }
  }

  const int g = lane >> 2;
  const int t4 = lane & 3;
  const bool f16out = (z == 2);
#pragma unroll
  for (int mi = 0; mi < 2; mi++) {
    int mrow = m0 + wm + mi * 16 + g;
    int b = mrow >> 11;
    int s = mrow & (kS - 1);
#pragma unroll
    for (int nf = 0; nf < 8; nf++) {
      int n = n0 + wn + nf * 8 + 2 * t4;
      int h = n >> 6;
      int d = n & 63;
      __nv_bfloat16* base = out + (((size_t)b * kH + h) * kS) * kD + d;
      unsigned p0, p1;
      if (f16out) {
        p0 = pack_f16x2(acc[mi][nf][0], acc[mi][nf][1]);
        p1 = pack_f16x2(acc[mi][nf][2], acc[mi][nf][3]);
      } else {
        p0 = pack_bf16x2(acc[mi][nf][0], acc[mi][nf][1]);
        p1 = pack_bf16x2(acc[mi][nf][2], acc[mi][nf][3]);
      }
      *(unsigned*)(base + (size_t)s * kD) = p0;
      *(unsigned*)(base + (size_t)(s + 8) * kD) = p1;
    }
  }
}

// ---------------------------------------------------------------------------
// Out-projection GEMM + residual: CTA 64x64x32 (fine grain to kill the 1.15-
// wave tail: grid = 1024 CTAs -> ~6.9/SM). 128 threads / 4 warps (2m x 2n),
// warp tile 32x32. 4-stage ring. g_x = ctx @ Wo + dec (fp32).
// ---------------------------------------------------------------------------
constexpr int OBPAD = 72;
constexpr int OB_STG = 32 * OBPAD;  // 2304
constexpr int OUT_SMEM = 4 * (A_STG + OB_STG) * 2;  // 38912 B

__global__ __launch_bounds__(128, 3) void out_gemm(const float* __restrict__ resid) {
  extern __shared__ __nv_bfloat16 osm[];
  __nv_bfloat16* AsB = osm;              // [4][64][APAD]
  __nv_bfloat16* BsB = osm + 4 * A_STG;  // [4][32][OBPAD]

  const int tid = threadIdx.x;
  const int lane = tid & 31;
  const int w = tid >> 5;  // 0..3
  const int m0 = blockIdx.y * 64;
  const int n0 = blockIdx.x * 64;
  const int wm = (w >> 1) * 32;
  const int wn = (w & 1) * 32;

  const __nv_bfloat16* A = g_ctxb;
  const __nv_bfloat16* Bw = g_wo;

  auto load_stage = [&](int j) {
    const int stg = j & 3;
    __nv_bfloat16* as = AsB + stg * A_STG;
    __nv_bfloat16* bs = BsB + stg * OB_STG;
    const int k0 = j * 32;
#pragma unroll
    for (int it = 0; it < 2; it++) {
      int ch = tid + it * 128;
      int rowA = ch >> 2, cA = (ch & 3) * 8;
      cpasync16(smem_u32(as + rowA * APAD + cA),
                A + (size_t)(m0 + rowA) * kE + k0 + cA);
    }
#pragma unroll
    for (int it = 0; it < 2; it++) {
      int ch = tid + it * 128;
      int rowB = ch >> 3, cB = (ch & 7) * 8;
      cpasync16(smem_u32(bs + rowB * OBPAD + cB),
                Bw + (size_t)(k0 + rowB) * kE + n0 + cB);
    }
  };

#pragma unroll
  for (int s = 0; s < 3; s++) {
    load_stage(s);
    cp_commit();
  }

  float acc[2][4][4];
#pragma unroll
  for (int mi = 0; mi < 2; mi++)
#pragma unroll
    for (int nf = 0; nf < 4; nf++)
#pragma unroll
      for (int c = 0; c < 4; c++) acc[mi][nf][c] = 0.f;

  const int lr = lane & 15;
  const int lc = lane >> 4;

  const int nK = kE / 32;  // 32
  for (int kt = 0; kt < nK; kt++) {
    cp_wait2();
    __syncthreads();
    if (kt + 3 < nK) load_stage(kt + 3);
    cp_commit();

    const __nv_bfloat16* as = AsB + (kt & 3) * A_STG;
    const __nv_bfloat16* bs = BsB + (kt & 3) * OB_STG;
#pragma unroll
    for (int ks = 0; ks < 2; ks++) {
      const int kk = ks * 16;
      unsigned af[2][4];
#pragma unroll
      for (int mi = 0; mi < 2; mi++)
        ldsm4(af[mi], smem_u32(as + (wm + mi * 16 + lr) * APAD + kk + lc * 8));
#pragma unroll
      for (int nj = 0; nj < 2; nj++) {
        unsigned bfr[4];
        ldsm4t(bfr, smem_u32(bs + (kk + lr) * OBPAD + wn + nj * 16 + lc * 8));
#pragma unroll
        for (int mi = 0; mi < 2; mi++) {
          mma16816(acc[mi][2 * nj + 0], af[mi], bfr[0], bfr[1]);
          mma16816(acc[mi][2 * nj + 1], af[mi], bfr[2], bfr[3]);
        }
      }
    }
  }

  const int g = lane >> 2;
  const int t4 = lane & 3;
#pragma unroll
  for (int mi = 0; mi < 2; mi++) {
    size_t m1 = (size_t)(m0 + wm + mi * 16 + g);
    size_t m2 = m1 + 8;
#pragma unroll
    for (int nf = 0; nf < 4; nf++) {
      int n = n0 + wn + nf * 8 + 2 * t4;
      float2 r0 = *(const float2*)(resid + m1 * kE + n);
      float2 r1 = *(const float2*)(resid + m2 * kE + n);
      *(float2*)(g_x + m1 * kE + n) =
          make_float2(acc[mi][nf][0] + r0.x, acc[mi][nf][1] + r0.y);
      *(float2*)(g_x + m2 * kE + n) =
          make_float2(acc[mi][nf][2] + r1.x, acc[mi][nf][3] + r1.y);
    }
  }
}

// ---------------------------------------------------------------------------
// Flash attention (R10 exact config): TQ=128, 4 warps x 32 q-rows, Tk=64,
// 4-stage cp.async ring, occ 2. QK bf16 MMA (log2 scores, scale in Wq),
// exp via ex2.approx.f16x2 (result IS the fp16 P fragment), PV fp16 MMA.
// ---------------------------------------------------------------------------
constexpr int TQ = 128;
constexpr int TK = 64;
constexpr int PAD = 72;
constexpr int KV_STG = TK * PAD;
constexpr int ATTN_SMEM = (TQ * PAD + 2 * 4 * KV_STG) * 2;  // 92160 B

__global__ __launch_bounds__(128, 2) void attn_kernel() {
  extern __shared__ __nv_bfloat16 sm[];
  __nv_bfloat16* Qs = sm;               // [128][72]
  __nv_bfloat16* Ks = sm + TQ * PAD;    // [4][64][72]
  __nv_bfloat16* Vs = Ks + 4 * KV_STG;  // [4][64][72] (fp16 bits)

  const int tid = threadIdx.x;
  const int lane = tid & 31;
  const int w = tid >> 5;  // 0..3
  const int bh = blockIdx.y;
  const int q0 = blockIdx.x * TQ;

  const __nv_bfloat16* gq = g_qb + (size_t)bh * kS * kD + (size_t)q0 * kD;
  const __nv_bfloat16* gk = g_kb + (size_t)bh * kS * kD;
  const __nv_bfloat16* gv = g_vb + (size_t)bh * kS * kD;

  auto load_kv = [&](int stg, int tile) {
    const __nv_bfloat16* k2 = gk + (size_t)tile * TK * kD;
    const __nv_bfloat16* v2 = gv + (size_t)tile * TK * kD;
#pragma unroll
    for (int it = 0; it < 4; it++) {
      int ch = tid + it * 128;
      int row = ch >> 3, c = (ch & 7) * 8;
      cpasync16(smem_u32(Ks + stg * KV_STG + row * PAD + c),
                k2 + (size_t)row * kD + c);
      cpasync16(smem_u32(Vs + stg * KV_STG + row * PAD + c),
                v2 + (size_t)row * kD + c);
    }
  };

#pragma unroll
  for (int s = 0; s < 3; s++) {
    load_kv(s, s);
    cp_commit();
  }

  for (int idx = tid; idx < TQ * 8; idx += 128) {
    int row = idx >> 3, c = (idx & 7) * 8;
    *(uint4*)(Qs + row * PAD + c) = *(const uint4*)(gq + (size_t)row * kD + c);
  }
  __syncthreads();

  const int lr = lane & 15;
  const int lc = lane >> 4;
  unsigned qa[2][4][4];
#pragma unroll
  for (int mi = 0; mi < 2; mi++) {
    const __nv_bfloat16* qp = Qs + (w * 32 + mi * 16 + lr) * PAD + lc * 8;
#pragma unroll
    for (int kt = 0; kt < 4; kt++) ldsm4(qa[mi][kt], smem_u32(qp + kt * 16));
  }

  float oa[2][8][4];
#pragma unroll
  for (int mi = 0; mi < 2; mi++)
#pragma unroll
    for (int j = 0; j < 8; j++)
#pragma unroll
      for (int c = 0; c < 4; c++) oa[mi][j][c] = 0.f;
  float lsum[2][2] = {{0.f, 0.f}, {0.f, 0.f}};

  const int nT = kS / TK;  // 32
  for (int ti = 0; ti < nT; ti++) {
    const int stg = ti & 3;
    cp_wait2();
    __syncthreads();
    if (ti + 3 < nT) load_kv((ti + 3) & 3, ti + 3);
    cp_commit();

    const __nv_bfloat16* kbp = Ks + stg * KV_STG;
    const __nv_bfloat16* vbp = Vs + stg * KV_STG;

    float sc[2][8][4];
#pragma unroll
    for (int mi = 0; mi < 2; mi++)
#pragma unroll
      for (int j = 0; j < 8; j++)
#pragma unroll
        for (int c = 0; c < 4; c++) sc[mi][j][c] = 0.f;
#pragma unroll
    for (int kt = 0; kt < 4; kt++) {
#pragma unroll
      for (int ng = 0; ng < 4; ng++) {
        unsigned kr[4];
        ldsm4(kr, smem_u32(kbp + (ng * 16 + lr) * PAD + kt * 16 + lc * 8));
#pragma unroll
        for (int mi = 0; mi < 2; mi++) {
          mma16816(sc[mi][2 * ng + 0], qa[mi][kt], kr[0], kr[2]);
          mma16816(sc[mi][2 * ng + 1], qa[mi][kt], kr[1], kr[3]);
        }
      }
    }

    unsigned pa[2][4][4];
#pragma unroll
    for (int mi = 0; mi < 2; mi++) {
      unsigned a0 = 0, a1 = 0;
#pragma unroll
      for (int j = 0; j < 8; j++) {
        unsigned s01 = pack_f16x2(sc[mi][j][0], sc[mi][j][1]);
        unsigned s23 = pack_f16x2(sc[mi][j][2], sc[mi][j][3]);
        unsigned w01 = ex2h2(s01);
        unsigned w23 = ex2h2(s23);
        a0 = hadd2u(a0, w01);
        a1 = hadd2u(a1, w23);
        int q = j >> 1;
        if (j & 1) {
          pa[mi][q][2] = w01;
          pa[mi][q][3] = w23;
        } else {
          pa[mi][q][0] = w01;
          pa[mi][q][1] = w23;
        }
      }
      float2 f0 = h2_to_f2(a0);
      float2 f1 = h2_to_f2(a1);
      lsum[mi][0] += f0.x + f0.y;
      lsum[mi][1] += f1.x + f1.y;
    }

#pragma unroll
    for (int kt = 0; kt < 4; kt++) {
#pragma unroll
      for (int dg = 0; dg < 4; dg++) {
        unsigned vr[4];
        ldsm4t(vr, smem_u32(vbp + (kt * 16 + lr) * PAD + dg * 16 + lc * 8));
#pragma unroll
        for (int mi = 0; mi < 2; mi++) {
          mma16816h(oa[mi][2 * dg + 0], pa[mi][kt], vr[0], vr[1]);
          mma16816h(oa[mi][2 * dg + 1], pa[mi][kt], vr[2], vr[3]);
        }
      }
    }
  }

  const int g = lane >> 2, t = lane & 3;
  const int b = bh >> 4, h = bh & 15;
#pragma unroll
  for (int mi = 0; mi < 2; mi++) {
    float l0 = lsum[mi][0], l1 = lsum[mi][1];
    l0 += __shfl_xor_sync(0xffffffffu, l0, 1);
    l0 += __shfl_xor_sync(0xffffffffu, l0, 2);
    l1 += __shfl_xor_sync(0xffffffffu, l1, 1);
    l1 += __shfl_xor_sync(0xffffffffu, l1, 2);
    const float il0 = 1.f / l0;
    const float il1 = 1.f / l1;
    const size_t row0 = (size_t)b * kS + q0 + w * 32 + mi * 16 + g;
    __nv_bfloat16* base0 = g_ctxb + row0 * kE + h * 64 + 2 * t;
    __nv_bfloat16* base1 = base0 + (size_t)8 * kE;
#pragma unroll
    for (int j = 0; j < 8; j++) {
      *(unsigned*)(base0 + 8 * j) =
          pack_bf16x2(oa[mi][j][0] * il0, oa[mi][j][1] * il0);
      *(unsigned*)(base1 + 8 * j) =
          pack_bf16x2(oa[mi][j][2] * il1, oa[mi][j][3] * il1);
    }
  }
}

// ---------------------------------------------------------------------------
// LayerNorm over last dim (1024): fp32 in/out.
// ---------------------------------------------------------------------------
__global__ __launch_bounds__(256) void ln_kernel(
    const float* __restrict__ gamma, const float* __restrict__ beta,
    float* __restrict__ out) {
  __shared__ float red[8];
  __shared__ float red2[8];
  const int m = blockIdx.x;
  const int tid = threadIdx.x;
  float4 v = *(const float4*)(g_x + (size_t)m * kE + tid * 4);
  float s = v.x + v.y + v.z + v.w;
#pragma unroll
  for (int off = 16; off > 0; off >>= 1) s += __shfl_xor_sync(0xffffffffu, s, off);
  if ((tid & 31) == 0) red[tid >> 5] = s;
  __syncthreads();
  float tot = red[0] + red[1] + red[2] + red[3] + red[4] + red[5] + red[6] + red[7];
  float mu = tot * (1.f / kE);
  float dx = v.x - mu, dy = v.y - mu, dz = v.z - mu, dw = v.w - mu;
  float sq = dx * dx + dy * dy + dz * dz + dw * dw;
#pragma unroll
  for (int off = 16; off > 0; off >>= 1) sq += __shfl_xor_sync(0xffffffffu, sq, off);
  if ((tid & 31) == 0) red2[tid >> 5] = sq;
  __syncthreads();
  float var =
      (red2[0] + red2[1] + red2[2] + red2[3] + red2[4] + red2[5] + red2[6] + red2[7]) *
      (1.f / kE);
  float rstd = rsqrtf(var + 1e-5f);
  float4 g = *(const float4*)(gamma + tid * 4);
  float4 be = *(const float4*)(beta + tid * 4);
  float4 o = make_float4(dx * rstd * g.x + be.x, dy * rstd * g.y + be.y,
                         dz * rstd * g.z + be.z, dw * rstd * g.w + be.w);
  *(float4*)(out + (size_t)m * kE + tid * 4) = o;
}

// ---------------------------------------------------------------------------
extern "C" void kernel_launch(void* const* d_in, const int* in_sizes, int n_in,
                              void* d_out, int out_size) {
  const float* enc = (const float*)d_in[0];
  const float* dec = (const float*)d_in[1];
  const float* Wq = (const float*)d_in[2];
  const float* Wk = (const float*)d_in[3];
  const float* Wv = (const float*)d_in[4];
  const float* Wo = (const float*)d_in[5];
  const float* gamma = (const float*)d_in[6];
  const float* beta = (const float*)d_in[7];
  float* out = (float*)d_out;

  cudaFuncSetAttribute(attn_kernel, cudaFuncAttributeMaxDynamicSharedMemorySize,
                       ATTN_SMEM);
  cudaFuncSetAttribute(gemm_qkv, cudaFuncAttributeMaxDynamicSharedMemorySize,
                       GEMM_SMEM);
  cudaFuncSetAttribute(out_gemm, cudaFuncAttributeMaxDynamicSharedMemorySize,
                       OUT_SMEM);

  // all converts in ONE launch (z = 0..5)
  cvt_all<<<dim3(kM * kE / 4096, 1, 6), 256>>>(enc, dec, Wq, Wk, Wv, Wo);

  // merged QKV GEMM: grid (N/128, M/64, 3) = 1536 CTAs
  gemm_qkv<<<dim3(kE / 128, kM / 64, 3), 128, GEMM_SMEM>>>();
  attn_kernel<<<dim3(kS / TQ, kB * kH), 128, ATTN_SMEM>>>();
  // out-proj: fine-grained 64x64 tiles -> 1024 CTAs (kills the 1.15-wave tail)
  out_gemm<<<dim3(kE / 64, kM / 64), 128, OUT_SMEM>>>(dec);
  ln_kernel<<<kM, 256>>>(gamma, beta, out);
}

// round 16
// speedup vs baseline: 1.0062x; 1.0061x over previous
#include <cuda_runtime.h>
#include <cuda_bf16.h>
#include <cuda_fp16.h>
#include <cstdint>
#include <cstring>

// Problem constants
constexpr int kB = 2;
constexpr int kS = 2048;
constexpr int kE = 1024;
constexpr int kH = 16;
constexpr int kD = 64;
constexpr int kM = kB * kS;  // 4096

// Scratch (static device globals)
__device__ __nv_bfloat16 g_encb[(size_t)kM * kE];
__device__ __nv_bfloat16 g_decb[(size_t)kM * kE];
__device__ __nv_bfloat16 g_wq[(size_t)kE * kE];  // [E][HD] n-major, pre-scaled
__device__ __nv_bfloat16 g_wk[(size_t)kE * kE];
__device__ __nv_bfloat16 g_wv[(size_t)kE * kE];
__device__ __nv_bfloat16 g_wo[(size_t)kE * kE];  // [HD][E] native
__device__ __nv_bfloat16 g_qb[(size_t)kB * kH * kS * kD];  // bf16 (scale in Wq)
__device__ __nv_bfloat16 g_kb[(size_t)kB * kH * kS * kD];  // bf16
__device__ __nv_bfloat16 g_vb[(size_t)kB * kH * kS * kD];  // fp16 bits
__device__ __nv_bfloat16 g_ctxb[(size_t)kM * kE];          // bf16 [b,s,h*D]
__device__ float g_x[(size_t)kM * kE];                     // pre-LN, fp32

// ---------------------------------------------------------------------------
// PTX helpers
// ---------------------------------------------------------------------------
__device__ __forceinline__ unsigned smem_u32(const void* p) {
  return (unsigned)__cvta_generic_to_shared(p);
}
__device__ __forceinline__ void ldsm4(unsigned* r, unsigned a) {
  asm volatile(
      "ldmatrix.sync.aligned.m8n8.x4.shared.b16 {%0,%1,%2,%3},[%4];\n"
      : "=r"(r[0]), "=r"(r[1]), "=r"(r[2]), "=r"(r[3])
      : "r"(a));
}
__device__ __forceinline__ void ldsm4t(unsigned* r, unsigned a) {
  asm volatile(
      "ldmatrix.sync.aligned.m8n8.x4.trans.shared.b16 {%0,%1,%2,%3},[%4];\n"
      : "=r"(r[0]), "=r"(r[1]), "=r"(r[2]), "=r"(r[3])
      : "r"(a));
}
__device__ __forceinline__ void mma16816(float* d, const unsigned* a, unsigned b0,
                                         unsigned b1) {
  asm volatile(
      "mma.sync.aligned.m16n8k16.row.col.f32.bf16.bf16.f32 "
      "{%0,%1,%2,%3},{%4,%5,%6,%7},{%8,%9},{%0,%1,%2,%3};\n"
      : "+f"(d[0]), "+f"(d[1]), "+f"(d[2]), "+f"(d[3])
      : "r"(a[0]), "r"(a[1]), "r"(a[2]), "r"(a[3]), "r"(b0), "r"(b1));
}
__device__ __forceinline__ void mma16816h(float* d, const unsigned* a, unsigned b0,
                                          unsigned b1) {
  asm volatile(
      "mma.sync.aligned.m16n8k16.row.col.f32.f16.f16.f32 "
      "{%0,%1,%2,%3},{%4,%5,%6,%7},{%8,%9},{%0,%1,%2,%3};\n"
      : "+f"(d[0]), "+f"(d[1]), "+f"(d[2]), "+f"(d[3])
      : "r"(a[0]), "r"(a[1]), "r"(a[2]), "r"(a[3]), "r"(b0), "r"(b1));
}
__device__ __forceinline__ void cpasync16(unsigned s, const void* g) {
  asm volatile("cp.async.cg.shared.global [%0],[%1],16;\n" ::"r"(s), "l"(g)
               : "memory");
}
__device__ __forceinline__ void cp_commit() {
  asm volatile("cp.async.commit_group;\n" ::: "memory");
}
__device__ __forceinline__ void cp_wait2() {
  asm volatile("cp.async.wait_group 2;\n" ::: "memory");
}
__device__ __forceinline__ unsigned pack_bf16x2(float lo, float hi) {
  __nv_bfloat162 t = __floats2bfloat162_rn(lo, hi);
  unsigned u;
  memcpy(&u, &t, 4);
  return u;
}
__device__ __forceinline__ unsigned pack_f16x2(float lo, float hi) {
  unsigned u;
  asm("cvt.rn.f16x2.f32 %0, %1, %2;" : "=r"(u) : "f"(hi), "f"(lo));
  return u;
}
__device__ __forceinline__ unsigned ex2h2(unsigned x) {
  unsigned r;
  asm("ex2.approx.f16x2 %0, %1;" : "=r"(r) : "r"(x));
  return r;
}
__device__ __forceinline__ unsigned hadd2u(unsigned a, unsigned b) {
  unsigned r;
  asm("add.f16x2 %0, %1, %2;" : "=r"(r) : "r"(a), "r"(b));
  return r;
}
__device__ __forceinline__ float2 h2_to_f2(unsigned u) {
  __half2 h;
  memcpy(&h, &u, 4);
  return __half22float2(h);
}

// ---------------------------------------------------------------------------
// Unified converter: ONE launch for all 6 conversion tasks.
// ---------------------------------------------------------------------------
__global__ __launch_bounds__(256) void cvt_all(
    const float* __restrict__ enc, const float* __restrict__ dec,
    const float* __restrict__ wq, const float* __restrict__ wk,
    const float* __restrict__ wv, const float* __restrict__ wo) {
  const int z = blockIdx.z;
  const int nblk = (z < 2) ? (kM * kE / 4096) : (kE * kE / 4096);
  if (blockIdx.x >= nblk) return;
  size_t i = ((size_t)blockIdx.x * 256 + threadIdx.x) * 16;

  const float* src;
  switch (z) {
    case 0: src = enc; break;
    case 1: src = dec; break;
    case 2: src = wq; break;
    case 3: src = wk; break;
    case 4: src = wv; break;
    default: src = wo; break;
  }
  const float scl = (z == 2) ? 0.125f * 1.4426950408889634f : 1.0f;
  float4 v0 = *(const float4*)(src + i);
  float4 v1 = *(const float4*)(src + i + 4);
  float4 v2 = *(const float4*)(src + i + 8);
  float4 v3 = *(const float4*)(src + i + 12);
  unsigned p[8];
  p[0] = pack_bf16x2(v0.x * scl, v0.y * scl);
  p[1] = pack_bf16x2(v0.z * scl, v0.w * scl);
  p[2] = pack_bf16x2(v1.x * scl, v1.y * scl);
  p[3] = pack_bf16x2(v1.z * scl, v1.w * scl);
  p[4] = pack_bf16x2(v2.x * scl, v2.y * scl);
  p[5] = pack_bf16x2(v2.z * scl, v2.w * scl);
  p[6] = pack_bf16x2(v3.x * scl, v3.y * scl);
  p[7] = pack_bf16x2(v3.z * scl, v3.w * scl);

  __nv_bfloat16* o;
  if (z == 0) {
    o = g_encb + i;
  } else if (z == 1) {
    o = g_decb + i;
  } else if (z == 5) {
    o = g_wo + i;
  } else {
    __nv_bfloat16* dst = (z == 2) ? g_wq : (z == 3) ? g_wk : g_wv;
    int h = (int)(i >> 16);
    int rem = (int)(i & 65535);
    int e = rem >> 6;
    int d = rem & 63;
    o = dst + (size_t)e * kE + h * kD + d;
  }
  *(uint4*)o = *(uint4*)&p[0];
  *(uint4*)(o + 8) = *(uint4*)&p[4];
}

// ---------------------------------------------------------------------------
// QKV GEMM (R11-proven): CTA 64x128x32, 128 threads / 4 warps (2m x 2n),
// warp tile 32x64. B [K][N] n-major, ldsm4t. 4-stage ring, 3 CTAs/SM.
// blockIdx.z selects Q/K/V (z==2 packs fp16 for V; Q scale folded into Wq).
// ---------------------------------------------------------------------------
constexpr int APAD = 40;
constexpr int BPAD = 136;
constexpr int A_STG = 64 * APAD;   // 2560
constexpr int B_STG = 32 * BPAD;   // 4352
constexpr int GEMM_SMEM = 4 * (A_STG + B_STG) * 2;  // 55296 B

__global__ __launch_bounds__(128, 3) void gemm_qkv() {
  extern __shared__ __nv_bfloat16 gsm[];
  __nv_bfloat16* AsB = gsm;              // [4][64][APAD]
  __nv_bfloat16* BsB = gsm + 4 * A_STG;  // [4][32][BPAD]

  const int tid = threadIdx.x;
  const int lane = tid & 31;
  const int w = tid >> 5;  // 0..3
  const int m0 = blockIdx.y * 64;
  const int n0 = blockIdx.x * 128;
  const int wm = (w >> 1) * 32;
  const int wn = (w & 1) * 64;

  const int z = blockIdx.z;
  const __nv_bfloat16* A = (z == 0) ? g_decb : g_encb;
  const __nv_bfloat16* Bw = (z == 0) ? g_wq : (z == 1) ? g_wk : g_wv;
  __nv_bfloat16* out = (z == 0) ? g_qb : (z == 1) ? g_kb : g_vb;

  auto load_stage = [&](int j) {
    const int stg = j & 3;
    __nv_bfloat16* as = AsB + stg * A_STG;
    __nv_bfloat16* bs = BsB + stg * B_STG;
    const int k0 = j * 32;
#pragma unroll
    for (int it = 0; it < 2; it++) {
      int ch = tid + it * 128;
      int rowA = ch >> 2, cA = (ch & 3) * 8;
      cpasync16(smem_u32(as + rowA * APAD + cA),
                A + (size_t)(m0 + rowA) * kE + k0 + cA);
    }
#pragma unroll
    for (int it = 0; it < 4; it++) {
      int ch = tid + it * 128;
      int rowB = ch >> 4, cB = (ch & 15) * 8;
      cpasync16(smem_u32(bs + rowB * BPAD + cB),
                Bw + (size_t)(k0 + rowB) * kE + n0 + cB);
    }
  };

#pragma unroll
  for (int s = 0; s < 3; s++) {
    load_stage(s);
    cp_commit();
  }

  float acc[2][8][4];
#pragma unroll
  for (int mi = 0; mi < 2; mi++)
#pragma unroll
    for (int nf = 0; nf < 8; nf++)
#pragma unroll
      for (int c = 0; c < 4; c++) acc[mi][nf][c] = 0.f;

  const int lr = lane & 15;
  const int lc = lane >> 4;

  const int nK = kE / 32;  // 32
  for (int kt = 0; kt < nK; kt++) {
    cp_wait2();
    __syncthreads();
    if (kt + 3 < nK) load_stage(kt + 3);
    cp_commit();

    const __nv_bfloat16* as = AsB + (kt & 3) * A_STG;
    const __nv_bfloat16* bs = BsB + (kt & 3) * B_STG;
#pragma unroll
    for (int ks = 0; ks < 2; ks++) {
      const int kk = ks * 16;
      unsigned af[2][4];
#pragma unroll
      for (int mi = 0; mi < 2; mi++)
        ldsm4(af[mi], smem_u32(as + (wm + mi * 16 + lr) * APAD + kk + lc * 8));
#pragma unroll
      for (int nj = 0; nj < 4; nj++) {
        unsigned bfr[4];
        ldsm4t(bfr, smem_u32(bs + (kk + lr) * BPAD + wn + nj * 16 + lc * 8));
#pragma unroll
        for (int mi = 0; mi < 2; mi++) {
          mma16816(acc[mi][2 * nj + 0], af[mi], bfr[0], bfr[1]);
          mma16816(acc[mi][2 * nj + 1], af[mi], bfr[2], bfr[3]);
        }
      }
    }
  }

  const int g = lane >> 2;
  const int t4 = lane & 3;
  const bool f16out = (z == 2);
#pragma unroll
  for (int mi = 0; mi < 2; mi++) {
    int mrow = m0 + wm + mi * 16 + g;
    int b = mrow >> 11;
    int s = mrow & (kS - 1);
#pragma unroll
    for (int nf = 0; nf < 8; nf++) {
      int n = n0 + wn + nf * 8 + 2 * t4;
      int h = n >> 6;
      int d = n & 63;
      __nv_bfloat16* base = out + (((size_t)b * kH + h) * kS) * kD + d;
      unsigned p0, p1;
      if (f16out) {
        p0 = pack_f16x2(acc[mi][nf][0], acc[mi][nf][1]);
        p1 = pack_f16x2(acc[mi][nf][2], acc[mi][nf][3]);
      } else {
        p0 = pack_bf16x2(acc[mi][nf][0], acc[mi][nf][1]);
        p1 = pack_bf16x2(acc[mi][nf][2], acc[mi][nf][3]);
      }
      *(unsigned*)(base + (size_t)s * kD) = p0;
      *(unsigned*)(base + (size_t)(s + 8) * kD) = p1;
    }
  }
}

// ---------------------------------------------------------------------------
// Out-projection GEMM + residual (R9/R10 big-tile config): CTA 128x128x32,
// 256 threads / 8 warps (2m x 4n), warp tile 64x32. Grid (8,32) = 256 CTAs
// = exactly one wave at occ 2; L2 traffic 128 MB (half of 64x64 tiling).
// g_x = ctx @ Wo + dec (fp32).
// ---------------------------------------------------------------------------
constexpr int OA_STG = 128 * APAD;  // 5120
constexpr int OUT_SMEM = 4 * (OA_STG + B_STG) * 2;  // 75776 B

__global__ __launch_bounds__(256, 2) void out_gemm(const float* __restrict__ resid) {
  extern __shared__ __nv_bfloat16 osm[];
  __nv_bfloat16* AsB = osm;               // [4][128][APAD]
  __nv_bfloat16* BsB = osm + 4 * OA_STG;  // [4][32][BPAD]

  const int tid = threadIdx.x;
  const int lane = tid & 31;
  const int w = tid >> 5;
  const int m0 = blockIdx.y * 128;
  const int n0 = blockIdx.x * 128;
  const int m_w = (w >> 2) * 64;
  const int n_w = (w & 3) * 32;

  const __nv_bfloat16* A = g_ctxb;
  const __nv_bfloat16* Bw = g_wo;

  auto load_stage = [&](int j) {
    const int stg = j & 3;
    __nv_bfloat16* as = AsB + stg * OA_STG;
    __nv_bfloat16* bs = BsB + stg * B_STG;
    const int k0 = j * 32;
#pragma unroll
    for (int it = 0; it < 2; it++) {
      int chunk = tid + it * 256;
      int rowA = chunk >> 2, cA = (chunk & 3) * 8;
      cpasync16(smem_u32(as + rowA * APAD + cA),
                A + (size_t)(m0 + rowA) * kE + k0 + cA);
      int rowB = chunk >> 4, cB = (chunk & 15) * 8;
      cpasync16(smem_u32(bs + rowB * BPAD + cB),
                Bw + (size_t)(k0 + rowB) * kE + n0 + cB);
    }
  };

#pragma unroll
  for (int s = 0; s < 3; s++) {
    load_stage(s);
    cp_commit();
  }

  float acc[4][4][4];
#pragma unroll
  for (int mi = 0; mi < 4; mi++)
#pragma unroll
    for (int nf = 0; nf < 4; nf++)
#pragma unroll
      for (int c = 0; c < 4; c++) acc[mi][nf][c] = 0.f;

  const int lr = lane & 15;
  const int lc = lane >> 4;

  const int nK = kE / 32;  // 32
  for (int kt = 0; kt < nK; kt++) {
    cp_wait2();
    __syncthreads();
    if (kt + 3 < nK) load_stage(kt + 3);
    cp_commit();

    const __nv_bfloat16* as = AsB + (kt & 3) * OA_STG;
    const __nv_bfloat16* bs = BsB + (kt & 3) * B_STG;
#pragma unroll
    for (int ks = 0; ks < 2; ks++) {
      const int kk = ks * 16;
      unsigned af[4][4];
#pragma unroll
      for (int mi = 0; mi < 4; mi++)
        ldsm4(af[mi], smem_u32(as + (m_w + mi * 16 + lr) * APAD + kk + lc * 8));
#pragma unroll
      for (int nj = 0; nj < 2; nj++) {
        unsigned bfr[4];
        ldsm4t(bfr, smem_u32(bs + (kk + lr) * BPAD + n_w + nj * 16 + lc * 8));
#pragma unroll
        for (int mi = 0; mi < 4; mi++) {
          mma16816(acc[mi][2 * nj + 0], af[mi], bfr[0], bfr[1]);
          mma16816(acc[mi][2 * nj + 1], af[mi], bfr[2], bfr[3]);
        }
      }
    }
  }

  const int g = lane >> 2;
  const int t4 = lane & 3;
#pragma unroll
  for (int mi = 0; mi < 4; mi++) {
    size_t m1 = (size_t)(m0 + m_w + mi * 16 + g);
    size_t m2 = m1 + 8;
#pragma unroll
    for (int nf = 0; nf < 4; nf++) {
      int n = n0 + n_w + nf * 8 + 2 * t4;
      float2 r0 = *(const float2*)(resid + m1 * kE + n);
      float2 r1 = *(const float2*)(resid + m2 * kE + n);
      *(float2*)(g_x + m1 * kE + n) =
          make_float2(acc[mi][nf][0] + r0.x, acc[mi][nf][1] + r0.y);
      *(float2*)(g_x + m2 * kE + n) =
          make_float2(acc[mi][nf][2] + r1.x, acc[mi][nf][3] + r1.y);
    }
  }
}

// ---------------------------------------------------------------------------
// Flash attention (R10 exact config): TQ=128, 4 warps x 32 q-rows, Tk=64,
// 4-stage cp.async ring, occ 2. QK bf16 MMA (log2 scores, scale in Wq),
// exp via ex2.approx.f16x2 (result IS the fp16 P fragment), PV fp16 MMA.
// ---------------------------------------------------------------------------
constexpr int TQ = 128;
constexpr int TK = 64;
constexpr int PAD = 72;
constexpr int KV_STG = TK * PAD;
constexpr int ATTN_SMEM = (TQ * PAD + 2 * 4 * KV_STG) * 2;  // 92160 B

__global__ __launch_bounds__(128, 2) void attn_kernel() {
  extern __shared__ __nv_bfloat16 sm[];
  __nv_bfloat16* Qs = sm;               // [128][72]
  __nv_bfloat16* Ks = sm + TQ * PAD;    // [4][64][72]
  __nv_bfloat16* Vs = Ks + 4 * KV_STG;  // [4][64][72] (fp16 bits)

  const int tid = threadIdx.x;
  const int lane = tid & 31;
  const int w = tid >> 5;  // 0..3
  const int bh = blockIdx.y;
  const int q0 = blockIdx.x * TQ;

  const __nv_bfloat16* gq = g_qb + (size_t)bh * kS * kD + (size_t)q0 * kD;
  const __nv_bfloat16* gk = g_kb + (size_t)bh * kS * kD;
  const __nv_bfloat16* gv = g_vb + (size_t)bh * kS * kD;

  auto load_kv = [&](int stg, int tile) {
    const __nv_bfloat16* k2 = gk + (size_t)tile * TK * kD;
    const __nv_bfloat16* v2 = gv + (size_t)tile * TK * kD;
#pragma unroll
    for (int it = 0; it < 4; it++) {
      int ch = tid + it * 128;
      int row = ch >> 3, c = (ch & 7) * 8;
      cpasync16(smem_u32(Ks + stg * KV_STG + row * PAD + c),
                k2 + (size_t)row * kD + c);
      cpasync16(smem_u32(Vs + stg * KV_STG + row * PAD + c),
                v2 + (size_t)row * kD + c);
    }
  };

#pragma unroll
  for (int s = 0; s < 3; s++) {
    load_kv(s, s);
    cp_commit();
  }

  for (int idx = tid; idx < TQ * 8; idx += 128) {
    int row = idx >> 3, c = (idx & 7) * 8;
    *(uint4*)(Qs + row * PAD + c) = *(const uint4*)(gq + (size_t)row * kD + c);
  }
  __syncthreads();

  const int lr = lane & 15;
  const int lc = lane >> 4;
  unsigned qa[2][4][4];
#pragma unroll
  for (int mi = 0; mi < 2; mi++) {
    const __nv_bfloat16* qp = Qs + (w * 32 + mi * 16 + lr) * PAD + lc * 8;
#pragma unroll
    for (int kt = 0; kt < 4; kt++) ldsm4(qa[mi][kt], smem_u32(qp + kt * 16));
  }

  float oa[2][8][4];
#pragma unroll
  for (int mi = 0; mi < 2; mi++)
#pragma unroll
    for (int j = 0; j < 8; j++)
#pragma unroll
      for (int c = 0; c < 4; c++) oa[mi][j][c] = 0.f;
  float lsum[2][2] = {{0.f, 0.f}, {0.f, 0.f}};

  const int nT = kS / TK;  // 32
  for (int ti = 0; ti < nT; ti++) {
    const int stg = ti & 3;
    cp_wait2();
    __syncthreads();
    if (ti + 3 < nT) load_kv((ti + 3) & 3, ti + 3);
    cp_commit();

    const __nv_bfloat16* kbp = Ks + stg * KV_STG;
    const __nv_bfloat16* vbp = Vs + stg * KV_STG;

    float sc[2][8][4];
#pragma unroll
    for (int mi = 0; mi < 2; mi++)
#pragma unroll
      for (int j = 0; j < 8; j++)
#pragma unroll
        for (int c = 0; c < 4; c++) sc[mi][j][c] = 0.f;
#pragma unroll
    for (int kt = 0; kt < 4; kt++) {
#pragma unroll
      for (int ng = 0; ng < 4; ng++) {
        unsigned kr[4];
        ldsm4(kr, smem_u32(kbp + (ng * 16 + lr) * PAD + kt * 16 + lc * 8));
#pragma unroll
        for (int mi = 0; mi < 2; mi++) {
          mma16816(sc[mi][2 * ng + 0], qa[mi][kt], kr[0], kr[2]);
          mma16816(sc[mi][2 * ng + 1], qa[mi][kt], kr[1], kr[3]);
        }
      }
    }

    unsigned pa[2][4][4];
#pragma unroll
    for (int mi = 0; mi < 2; mi++) {
      unsigned a0 = 0, a1 = 0;
#pragma unroll
      for (int j = 0; j < 8; j++) {
        unsigned s01 = pack_f16x2(sc[mi][j][0], sc[mi][j][1]);
        unsigned s23 = pack_f16x2(sc[mi][j][2], sc[mi][j][3]);
        unsigned w01 = ex2h2(s01);
        unsigned w23 = ex2h2(s23);
        a0 = hadd2u(a0, w01);
        a1 = hadd2u(a1, w23);
        int q = j >> 1;
        if (j & 1) {
          pa[mi][q][2] = w01;
          pa[mi][q][3] = w23;
        } else {
          pa[mi][q][0] = w01;
          pa[mi][q][1] = w23;
        }
      }
      float2 f0 = h2_to_f2(a0);
      float2 f1 = h2_to_f2(a1);
      lsum[mi][0] += f0.x + f0.y;
      lsum[mi][1] += f1.x + f1.y;
    }

#pragma unroll
    for (int kt = 0; kt < 4; kt++) {
#pragma unroll
      for (int dg = 0; dg < 4; dg++) {
        unsigned vr[4];
        ldsm4t(vr, smem_u32(vbp + (kt * 16 + lr) * PAD + dg * 16 + lc * 8));
#pragma unroll
        for (int mi = 0; mi < 2; mi++) {
          mma16816h(oa[mi][2 * dg + 0], pa[mi][kt], vr[0], vr[1]);
          mma16816h(oa[mi][2 * dg + 1], pa[mi][kt], vr[2], vr[3]);
        }
      }
    }
  }

  const int g = lane >> 2, t = lane & 3;
  const int b = bh >> 4, h = bh & 15;
#pragma unroll
  for (int mi = 0; mi < 2; mi++) {
    float l0 = lsum[mi][0], l1 = lsum[mi][1];
    l0 += __shfl_xor_sync(0xffffffffu, l0, 1);
    l0 += __shfl_xor_sync(0xffffffffu, l0, 2);
    l1 += __shfl_xor_sync(0xffffffffu, l1, 1);
    l1 += __shfl_xor_sync(0xffffffffu, l1, 2);
    const float il0 = 1.f / l0;
    const float il1 = 1.f / l1;
    const size_t row0 = (size_t)b * kS + q0 + w * 32 + mi * 16 + g;
    __nv_bfloat16* base0 = g_ctxb + row0 * kE + h * 64 + 2 * t;
    __nv_bfloat16* base1 = base0 + (size_t)8 * kE;
#pragma unroll
    for (int j = 0; j < 8; j++) {
      *(unsigned*)(base0 + 8 * j) =
          pack_bf16x2(oa[mi][j][0] * il0, oa[mi][j][1] * il0);
      *(unsigned*)(base1 + 8 * j) =
          pack_bf16x2(oa[mi][j][2] * il1, oa[mi][j][3] * il1);
    }
  }
}

// ---------------------------------------------------------------------------
// LayerNorm over last dim (1024): fp32 in/out.
// ---------------------------------------------------------------------------
__global__ __launch_bounds__(256) void ln_kernel(
    const float* __restrict__ gamma, const float* __restrict__ beta,
    float* __restrict__ out) {
  __shared__ float red[8];
  __shared__ float red2[8];
  const int m = blockIdx.x;
  const int tid = threadIdx.x;
  float4 v = *(const float4*)(g_x + (size_t)m * kE + tid * 4);
  float s = v.x + v.y + v.z + v.w;
#pragma unroll
  for (int off = 16; off > 0; off >>= 1) s += __shfl_xor_sync(0xffffffffu, s, off);
  if ((tid & 31) == 0) red[tid >> 5] = s;
  __syncthreads();
  float tot = red[0] + red[1] + red[2] + red[3] + red[4] + red[5] + red[6] + red[7];
  float mu = tot * (1.f / kE);
  float dx = v.x - mu, dy = v.y - mu, dz = v.z - mu, dw = v.w - mu;
  float sq = dx * dx + dy * dy + dz * dz + dw * dw;
#pragma unroll
  for (int off = 16; off > 0; off >>= 1) sq += __shfl_xor_sync(0xffffffffu, sq, off);
  if ((tid & 31) == 0) red2[tid >> 5] = sq;
  __syncthreads();
  float var =
      (red2[0] + red2[1] + red2[2] + red2[3] + red2[4] + red2[5] + red2[6] + red2[7]) *
      (1.f / kE);
  float rstd = rsqrtf(var + 1e-5f);
  float4 g = *(const float4*)(gamma + tid * 4);
  float4 be = *(const float4*)(beta + tid * 4);
  float4 o = make_float4(dx * rstd * g.x + be.x, dy * rstd * g.y + be.y,
                         dz * rstd * g.z + be.z, dw * rstd * g.w + be.w);
  *(float4*)(out + (size_t)m * kE + tid * 4) = o;
}

// ---------------------------------------------------------------------------
extern "C" void kernel_launch(void* const* d_in, const int* in_sizes, int n_in,
                              void* d_out, int out_size) {
  const float* enc = (const float*)d_in[0];
  const float* dec = (const float*)d_in[1];
  const float* Wq = (const float*)d_in[2];
  const float* Wk = (const float*)d_in[3];
  const float* Wv = (const float*)d_in[4];
  const float* Wo = (const float*)d_in[5];
  const float* gamma = (const float*)d_in[6];
  const float* beta = (const float*)d_in[7];
  float* out = (float*)d_out;

  cudaFuncSetAttribute(attn_kernel, cudaFuncAttributeMaxDynamicSharedMemorySize,
                       ATTN_SMEM);
  cudaFuncSetAttribute(gemm_qkv, cudaFuncAttributeMaxDynamicSharedMemorySize,
                       GEMM_SMEM);
  cudaFuncSetAttribute(out_gemm, cudaFuncAttributeMaxDynamicSharedMemorySize,
                       OUT_SMEM);

  // all converts in ONE launch (z = 0..5)
  cvt_all<<<dim3(kM * kE / 4096, 1, 6), 256>>>(enc, dec, Wq, Wk, Wv, Wo);

  // merged QKV GEMM: grid (N/128, M/64, 3) = 1536 CTAs
  gemm_qkv<<<dim3(kE / 128, kM / 64, 3), 128, GEMM_SMEM>>>();
  attn_kernel<<<dim3(kS / TQ, kB * kH), 128, ATTN_SMEM>>>();
  // out-proj: big 128x128 tiles -> 256 CTAs = one full wave, max L2 reuse
  out_gemm<<<dim3(kE / 128, kM / 128), 256, OUT_SMEM>>>(dec);
  ln_kernel<<<kM, 256>>>(gamma, beta, out);
}